// round 3
// baseline (speedup 1.0000x reference)
#include <cuda_runtime.h>
#include <cuda_bf16.h>
#include <cstdint>

constexpr int S_LEN = 4096;
constexpr int D_EMB = 512;
constexpr int D_HEAD = 64;

// Scratch (device globals; allocation-free requirement)
__device__ float g_Q[S_LEN * D_EMB];
__device__ float g_K[S_LEN * D_EMB];
__device__ float g_V[S_LEN * D_EMB];
__device__ float g_ctx[S_LEN * D_EMB];
__device__ float g_y[S_LEN * D_EMB];

// ---- f32x2 packed FMA helpers -------------------------------------------
__device__ __forceinline__ unsigned long long pk2(float x, float y) {
    unsigned long long r;
    asm("mov.b64 %0, {%1, %2};" : "=l"(r) : "f"(x), "f"(y));
    return r;
}
__device__ __forceinline__ void fma2(unsigned long long& d, unsigned long long a, unsigned long long b) {
    asm("fma.rn.f32x2 %0, %1, %2, %0;" : "+l"(d) : "l"(a), "l"(b));
}
__device__ __forceinline__ unsigned long long mul2(unsigned long long a, unsigned long long b) {
    unsigned long long d;
    asm("mul.rn.f32x2 %0, %1, %2;" : "=l"(d) : "l"(a), "l"(b));
    return d;
}
__device__ __forceinline__ float2 upk(unsigned long long v) {
    float2 r;
    asm("mov.b64 {%0, %1}, %2;" : "=f"(r.x), "=f"(r.y) : "l"(v));
    return r;
}

// ---- GEMM: C[4096,512] = A @ B[512,512] + bias (+ optional residual) ----
__device__ __forceinline__ void gemm_core(
    const float* __restrict__ A, const float* __restrict__ B,
    const float* __restrict__ bias, const float* __restrict__ res,
    float* __restrict__ C)
{
    constexpr int N = D_EMB, K = D_EMB;
    __shared__ float As[16][128];  // [k][m] (A transposed)
    __shared__ float Bs[16][128];  // [k][n]

    const int tid  = threadIdx.x;
    const int brow = blockIdx.y * 128;
    const int bcol = blockIdx.x * 128;
    const int trow = (tid >> 4) << 3;
    const int tcol = (tid & 15) << 3;

    unsigned long long acc[8][4];
#pragma unroll
    for (int i = 0; i < 8; ++i)
#pragma unroll
        for (int j = 0; j < 4; ++j) acc[i][j] = 0ull;

    for (int k0 = 0; k0 < K; k0 += 16) {
        __syncthreads();
#pragma unroll
        for (int i = tid; i < 512; i += 256) {
            int r = i >> 2, c4 = (i & 3) << 2;
            float4 v = *(const float4*)(A + (size_t)(brow + r) * K + k0 + c4);
            As[c4 + 0][r] = v.x; As[c4 + 1][r] = v.y;
            As[c4 + 2][r] = v.z; As[c4 + 3][r] = v.w;
        }
#pragma unroll
        for (int i = tid; i < 512; i += 256) {
            int r = i >> 5, c4 = (i & 31) << 2;
            *(float4*)(&Bs[r][c4]) = *(const float4*)(B + (size_t)(k0 + r) * N + bcol + c4);
        }
        __syncthreads();
#pragma unroll
        for (int k = 0; k < 16; ++k) {
            float4 a0 = *(const float4*)(&As[k][trow]);
            float4 a1 = *(const float4*)(&As[k][trow + 4]);
            float4 b0 = *(const float4*)(&Bs[k][tcol]);
            float4 b1 = *(const float4*)(&Bs[k][tcol + 4]);
            unsigned long long bp[4] = {pk2(b0.x, b0.y), pk2(b0.z, b0.w),
                                        pk2(b1.x, b1.y), pk2(b1.z, b1.w)};
            float av[8] = {a0.x, a0.y, a0.z, a0.w, a1.x, a1.y, a1.z, a1.w};
#pragma unroll
            for (int i = 0; i < 8; ++i) {
                unsigned long long ad = pk2(av[i], av[i]);
#pragma unroll
                for (int j = 0; j < 4; ++j) fma2(acc[i][j], ad, bp[j]);
            }
        }
    }
#pragma unroll
    for (int i = 0; i < 8; ++i) {
        const size_t r = (size_t)(brow + trow + i);
        float out[8];
#pragma unroll
        for (int j = 0; j < 4; ++j) {
            float2 v = upk(acc[i][j]);
            out[2 * j] = v.x; out[2 * j + 1] = v.y;
        }
#pragma unroll
        for (int j = 0; j < 8; ++j) out[j] += bias[bcol + tcol + j];
        if (res) {
#pragma unroll
            for (int j = 0; j < 8; ++j) out[j] += res[r * N + bcol + tcol + j];
        }
        *(float4*)(C + r * N + bcol + tcol)     = make_float4(out[0], out[1], out[2], out[3]);
        *(float4*)(C + r * N + bcol + tcol + 4) = make_float4(out[4], out[5], out[6], out[7]);
    }
}

__global__ __launch_bounds__(256) void qkv_kernel(
    const float* __restrict__ x,
    const float* __restrict__ Wq, const float* __restrict__ bq,
    const float* __restrict__ Wk, const float* __restrict__ bk,
    const float* __restrict__ Wv, const float* __restrict__ bv)
{
    const float *B, *bias; float* C;
    if (blockIdx.z == 0)      { B = Wq; bias = bq; C = g_Q; }
    else if (blockIdx.z == 1) { B = Wk; bias = bk; C = g_K; }
    else                      { B = Wv; bias = bv; C = g_V; }
    gemm_core(x, B, bias, nullptr, C);
}

__global__ __launch_bounds__(256) void outproj_kernel(
    const float* __restrict__ x,
    const float* __restrict__ Wo, const float* __restrict__ bo)
{
    gemm_core(g_ctx, Wo, bo, x, g_y);
}

// ---- Flash attention: BQ=128, BKV=64, 256 threads ------------------------
#define FBQ 128
#define FBKV 64
#define FP_PITCH 66
constexpr int FLASH_SMEM_FLOATS = 64 * 128 + 64 * 64 + 64 * 64 + 128 * FP_PITCH + 3 * 128;
constexpr int FLASH_SMEM_BYTES  = FLASH_SMEM_FLOATS * 4;

__global__ __launch_bounds__(256, 2) void flash_kernel()
{
    extern __shared__ float sm[];
    float* sQT = sm;                    // [64][128] d-major, pre-scaled
    float* sKT = sQT + 64 * 128;        // [64][64]  d-major
    float* sV  = sKT + 64 * 64;         // [64][64]  row-major
    float* sP  = sV + 64 * 64;          // [128][66]
    float* m_s = sP + 128 * FP_PITCH;
    float* l_s = m_s + 128;
    float* c_s = l_s + 128;

    const int tid = threadIdx.x;
    const int h   = blockIdx.y;
    const int q0  = blockIdx.x * FBQ;
    const int r0  = (tid >> 4) << 3;
    const int c0  = (tid & 15) << 2;

    for (int i = tid; i < FBQ * 16; i += 256) {
        int r = i >> 4, d4 = (i & 15) << 2;
        float4 v = *(const float4*)(g_Q + (size_t)(q0 + r) * D_EMB + h * D_HEAD + d4);
        sQT[(d4 + 0) * FBQ + r] = v.x * 0.125f;
        sQT[(d4 + 1) * FBQ + r] = v.y * 0.125f;
        sQT[(d4 + 2) * FBQ + r] = v.z * 0.125f;
        sQT[(d4 + 3) * FBQ + r] = v.w * 0.125f;
    }
    if (tid < FBQ) { m_s[tid] = -1e30f; l_s[tid] = 0.0f; }

    unsigned long long o2[8][2];
#pragma unroll
    for (int i = 0; i < 8; ++i) { o2[i][0] = 0ull; o2[i][1] = 0ull; }

    for (int kb = 0; kb < S_LEN; kb += FBKV) {
        __syncthreads();
        for (int i = tid; i < FBKV * 16; i += 256) {
            int r = i >> 4, d4 = (i & 15) << 2;
            float4 kv = *(const float4*)(g_K + (size_t)(kb + r) * D_EMB + h * D_HEAD + d4);
            sKT[(d4 + 0) * FBKV + r] = kv.x;
            sKT[(d4 + 1) * FBKV + r] = kv.y;
            sKT[(d4 + 2) * FBKV + r] = kv.z;
            sKT[(d4 + 3) * FBKV + r] = kv.w;
            *(float4*)(sV + r * 64 + d4) =
                *(const float4*)(g_V + (size_t)(kb + r) * D_EMB + h * D_HEAD + d4);
        }
        __syncthreads();

        unsigned long long s2[8][2];
#pragma unroll
        for (int i = 0; i < 8; ++i) { s2[i][0] = 0ull; s2[i][1] = 0ull; }
#pragma unroll 8
        for (int d = 0; d < 64; ++d) {
            float4 qa = *(const float4*)(sQT + d * FBQ + r0);
            float4 qb = *(const float4*)(sQT + d * FBQ + r0 + 4);
            float4 kk = *(const float4*)(sKT + d * FBKV + c0);
            unsigned long long kp0 = pk2(kk.x, kk.y);
            unsigned long long kp1 = pk2(kk.z, kk.w);
            float qv[8] = {qa.x, qa.y, qa.z, qa.w, qb.x, qb.y, qb.z, qb.w};
#pragma unroll
            for (int i = 0; i < 8; ++i) {
                unsigned long long qd = pk2(qv[i], qv[i]);
                fma2(s2[i][0], qd, kp0);
                fma2(s2[i][1], qd, kp1);
            }
        }
#pragma unroll
        for (int i = 0; i < 8; ++i) {
            *(unsigned long long*)(sP + (size_t)(r0 + i) * FP_PITCH + c0)     = s2[i][0];
            *(unsigned long long*)(sP + (size_t)(r0 + i) * FP_PITCH + c0 + 2) = s2[i][1];
        }
        __syncthreads();

        if (tid < FBQ) {
            float* prow = sP + (size_t)tid * FP_PITCH;
            float mo = m_s[tid], mx = mo;
#pragma unroll 16
            for (int j = 0; j < FBKV; ++j) mx = fmaxf(mx, prow[j]);
            float corr = __expf(mo - mx), sum = 0.0f;
#pragma unroll 16
            for (int j = 0; j < FBKV; ++j) {
                float p = __expf(prow[j] - mx);
                prow[j] = p; sum += p;
            }
            l_s[tid] = l_s[tid] * corr + sum;
            m_s[tid] = mx;
            c_s[tid] = corr;
        }
        __syncthreads();

#pragma unroll
        for (int i = 0; i < 8; ++i) {
            float cr = c_s[r0 + i];
            unsigned long long cd = pk2(cr, cr);
            o2[i][0] = mul2(o2[i][0], cd);
            o2[i][1] = mul2(o2[i][1], cd);
        }
#pragma unroll 8
        for (int jj = 0; jj < FBKV; ++jj) {
            float4 vv = *(const float4*)(sV + jj * 64 + c0);
            unsigned long long vp0 = pk2(vv.x, vv.y);
            unsigned long long vp1 = pk2(vv.z, vv.w);
#pragma unroll
            for (int i = 0; i < 8; ++i) {
                float p = sP[(size_t)(r0 + i) * FP_PITCH + jj];
                unsigned long long pd = pk2(p, p);
                fma2(o2[i][0], pd, vp0);
                fma2(o2[i][1], pd, vp1);
            }
        }
    }
#pragma unroll
    for (int i = 0; i < 8; ++i) {
        float inv = 1.0f / l_s[r0 + i];
        float2 p0 = upk(o2[i][0]);
        float2 p1 = upk(o2[i][1]);
        *(float4*)(g_ctx + (size_t)(q0 + r0 + i) * D_EMB + h * D_HEAD + c0) =
            make_float4(p0.x * inv, p0.y * inv, p1.x * inv, p1.y * inv);
    }
}

// ---- LayerNorm: one block per row ---------------------------------------
__global__ __launch_bounds__(128) void ln_kernel(
    const float* __restrict__ gamma, const float* __restrict__ beta,
    float* __restrict__ out)
{
    __shared__ float red[2][4];
    const int row = blockIdx.x, tid = threadIdx.x;
    const float* y = g_y + (size_t)row * D_EMB;

    float4 v = *(const float4*)(y + tid * 4);
    float s  = v.x + v.y + v.z + v.w;
    float sq = v.x * v.x + v.y * v.y + v.z * v.z + v.w * v.w;
#pragma unroll
    for (int o = 16; o > 0; o >>= 1) {
        s  += __shfl_xor_sync(0xFFFFFFFF, s, o);
        sq += __shfl_xor_sync(0xFFFFFFFF, sq, o);
    }
    if ((tid & 31) == 0) { red[0][tid >> 5] = s; red[1][tid >> 5] = sq; }
    __syncthreads();
    s  = red[0][0] + red[0][1] + red[0][2] + red[0][3];
    sq = red[1][0] + red[1][1] + red[1][2] + red[1][3];
    const float mu  = s * (1.0f / D_EMB);
    const float var = sq * (1.0f / D_EMB) - mu * mu;
    const float rstd = rsqrtf(var + 1e-5f);

    float4 g = *(const float4*)(gamma + tid * 4);
    float4 b = *(const float4*)(beta + tid * 4);
    float4 o;
    o.x = (v.x - mu) * rstd * g.x + b.x;
    o.y = (v.y - mu) * rstd * g.y + b.y;
    o.z = (v.z - mu) * rstd * g.z + b.z;
    o.w = (v.w - mu) * rstd * g.w + b.w;
    *(float4*)(out + (size_t)row * D_EMB + tid * 4) = o;
}

// ---- launch ---------------------------------------------------------------
extern "C" void kernel_launch(void* const* d_in, const int* in_sizes, int n_in,
                              void* d_out, int out_size)
{
    const float* x     = (const float*)d_in[0];
    const float* Wq    = (const float*)d_in[1];
    const float* bq    = (const float*)d_in[2];
    const float* Wk    = (const float*)d_in[3];
    const float* bk    = (const float*)d_in[4];
    const float* Wv    = (const float*)d_in[5];
    const float* bv    = (const float*)d_in[6];
    const float* Wo    = (const float*)d_in[7];
    const float* bo    = (const float*)d_in[8];
    const float* gamma = (const float*)d_in[9];
    const float* beta  = (const float*)d_in[10];
    float* out = (float*)d_out;

    cudaFuncSetAttribute(flash_kernel,
                         cudaFuncAttributeMaxDynamicSharedMemorySize,
                         FLASH_SMEM_BYTES);

    dim3 gq(D_EMB / 128, S_LEN / 128, 3);
    qkv_kernel<<<gq, 256>>>(x, Wq, bq, Wk, bk, Wv, bv);

    dim3 gflash(S_LEN / FBQ, 8);
    flash_kernel<<<gflash, 256, FLASH_SMEM_BYTES>>>();

    dim3 go(D_EMB / 128, S_LEN / 128);
    outproj_kernel<<<go, 256>>>(x, Wo, bo);

    ln_kernel<<<S_LEN, 128>>>(gamma, beta, out);
}